// round 1
// baseline (speedup 1.0000x reference)
#include <cuda_runtime.h>
#include <math.h>

#define NN 50000
#define NE 800000
#define HID 64
#define LAYERS 4
#define MLPH 128

// ---------------- device state (no allocs allowed) ----------------
__device__ float g_h[NN * HID];            // node state
__device__ float g_e[NE * HID];            // edge state, CSR-permuted order
__device__ float g_Ce[NE * HID];           // e @ W_C per layer
__device__ float g_nodeT[NN * 4 * HID];    // per node: [A|B|D|E] rows of 64
__device__ float g_mlp[NN * MLPH];
__device__ int   g_count[NN];
__device__ int   g_rowstart[NN + 1];
__device__ int   g_cursor[NN];
__device__ int   g_perm_src[NE];           // src per CSR position
__device__ int   g_perm_eid[NE];           // original edge id per CSR position

// ---------------- f32x2 packed helpers ----------------
__device__ __forceinline__ unsigned long long pack2(float x, float y) {
    unsigned long long r;
    asm("mov.b64 %0, {%1, %2};" : "=l"(r) : "f"(x), "f"(y));
    return r;
}
__device__ __forceinline__ void ffma2(unsigned long long& acc, unsigned long long a, unsigned long long b) {
    asm("fma.rn.f32x2 %0, %1, %2, %0;" : "+l"(acc) : "l"(a), "l"(b));
}
__device__ __forceinline__ float2 unpack2(unsigned long long v) {
    float x, y;
    asm("mov.b64 {%0, %1}, %2;" : "=f"(x), "=f"(y) : "l"(v));
    return make_float2(x, y);
}

// ---------------- CSR build ----------------
__global__ void k_zero() {
    int i = blockIdx.x * blockDim.x + threadIdx.x;
    if (i < NN) g_count[i] = 0;
}

__global__ void k_hist(const int* __restrict__ dst) {
    int e = blockIdx.x * blockDim.x + threadIdx.x;
    if (e < NE) atomicAdd(&g_count[dst[e]], 1);
}

__global__ void k_scan() {  // single block, 1024 threads
    __shared__ int part[1024];
    int tid = threadIdx.x;
    const int CH = (NN + 1023) / 1024;
    int base = tid * CH;
    int s = 0;
    for (int i = 0; i < CH; i++) {
        int idx = base + i;
        if (idx < NN) s += g_count[idx];
    }
    part[tid] = s;
    __syncthreads();
    for (int off = 1; off < 1024; off <<= 1) {
        int v = (tid >= off) ? part[tid - off] : 0;
        __syncthreads();
        part[tid] += v;
        __syncthreads();
    }
    int excl = part[tid] - s;
    for (int i = 0; i < CH; i++) {
        int idx = base + i;
        if (idx < NN) {
            g_rowstart[idx] = excl;
            g_cursor[idx] = excl;
            excl += g_count[idx];
        }
    }
    if (tid == 1023) g_rowstart[NN] = part[1023];
}

__global__ void k_scatter(const int* __restrict__ src, const int* __restrict__ dst) {
    int e = blockIdx.x * blockDim.x + threadIdx.x;
    if (e < NE) {
        int d = dst[e];
        int pos = atomicAdd(&g_cursor[d], 1);
        g_perm_src[pos] = src[e];
        g_perm_eid[pos] = e;
    }
}

// ---------------- input embeddings ----------------
__global__ void k_embed_h(const float* __restrict__ hf, const float* __restrict__ W,
                          const float* __restrict__ b) {
    int idx = blockIdx.x * blockDim.x + threadIdx.x;
    if (idx >= NN * HID) return;
    int n = idx >> 6, c = idx & 63;
    float s = b[c];
#pragma unroll
    for (int j = 0; j < 6; j++) s = fmaf(hf[n * 6 + j], W[j * HID + c], s);
    g_h[idx] = s;
}

__global__ void k_embed_e(const float* __restrict__ ef, const float* __restrict__ W,
                          const float* __restrict__ b) {
    int idx = blockIdx.x * blockDim.x + threadIdx.x;
    if (idx >= NE * HID) return;
    int p = idx >> 6, c = idx & 63;
    int eid = g_perm_eid[p];
    float s = b[c];
    s = fmaf(ef[eid * 2 + 0], W[c], s);
    s = fmaf(ef[eid * 2 + 1], W[HID + c], s);
    g_e[idx] = s;
}

// ---------------- shared-tiled GEMM: C[M,*] = A[M,64] @ W[64,64-tile] + bias ----------------
// grid.y selects 64-col tile: Wt = W + by*wtStride, reads Wt[k*ldw + c],
// output cols at by*64 within row stride ldc.
__global__ void __launch_bounds__(256) k_gemm64(
    const float* __restrict__ A, const float* __restrict__ W,
    const float* __restrict__ bias, float* __restrict__ C,
    int M, int ldw, int wtStride, int ldc, int relu)
{
    __shared__ float As[64][68];
    __shared__ float Ws[64][68];
    int by = blockIdx.y;
    const float* Wt = W + (size_t)by * wtStride;
    int n0 = blockIdx.x * 64;
    int t = threadIdx.x;
    int tx = t & 15, ty = t >> 4;

    // load A tile (row-major), coalesced float4
#pragma unroll
    for (int i = 0; i < 4; i++) {
        int q = i * 256 + t;
        int row = q >> 4;
        int kq = q & 15;
        int m = n0 + row;
        float4 v = make_float4(0.f, 0.f, 0.f, 0.f);
        if (m < M) v = *(const float4*)(A + (size_t)m * 64 + kq * 4);
        *(float4*)&As[row][kq * 4] = v;
    }
    // load W tile
#pragma unroll
    for (int i = 0; i < 4; i++) {
        int q = i * 256 + t;
        int k = q >> 4;
        int cq = q & 15;
        float4 v = *(const float4*)(Wt + (size_t)k * ldw + cq * 4);
        *(float4*)&Ws[k][cq * 4] = v;
    }
    __syncthreads();

    unsigned long long acc[4][2];
#pragma unroll
    for (int r = 0; r < 4; r++) { acc[r][0] = 0ull; acc[r][1] = 0ull; }

#pragma unroll 8
    for (int k = 0; k < 64; k++) {
        float4 b4 = *(const float4*)&Ws[k][tx * 4];
        unsigned long long bp0 = pack2(b4.x, b4.y);
        unsigned long long bp1 = pack2(b4.z, b4.w);
#pragma unroll
        for (int r = 0; r < 4; r++) {
            float a = As[ty * 4 + r][k];
            unsigned long long ap = pack2(a, a);
            ffma2(acc[r][0], ap, bp0);
            ffma2(acc[r][1], ap, bp1);
        }
    }

    float bb0 = bias[by * 64 + tx * 4 + 0];
    float bb1 = bias[by * 64 + tx * 4 + 1];
    float bb2 = bias[by * 64 + tx * 4 + 2];
    float bb3 = bias[by * 64 + tx * 4 + 3];
#pragma unroll
    for (int r = 0; r < 4; r++) {
        int m = n0 + ty * 4 + r;
        if (m < M) {
            float2 v0 = unpack2(acc[r][0]);
            float2 v1 = unpack2(acc[r][1]);
            float4 o;
            o.x = v0.x + bb0;
            o.y = v0.y + bb1;
            o.z = v1.x + bb2;
            o.w = v1.y + bb3;
            if (relu) {
                o.x = fmaxf(o.x, 0.f); o.y = fmaxf(o.y, 0.f);
                o.z = fmaxf(o.z, 0.f); o.w = fmaxf(o.w, 0.f);
            }
            *(float4*)(C + (size_t)m * ldc + by * 64 + tx * 4) = o;
        }
    }
}

// ---------------- fused edge gate + aggregation + node update ----------------
// one warp per dst node; num/den accumulated in registers (no atomics)
__global__ void k_edge() {
    int gtid = blockIdx.x * blockDim.x + threadIdx.x;
    int node = gtid >> 5;
    if (node >= NN) return;
    int lane = gtid & 31;

    const float* nt = g_nodeT + node * 256;
    float a0 = nt[lane],       a1 = nt[32 + lane];    // Ah
    float d0 = nt[128 + lane], d1 = nt[160 + lane];   // Dh (dst-invariant)
    float num0 = 0.f, num1 = 0.f, den0 = 0.f, den1 = 0.f;

    int rs = g_rowstart[node], re = g_rowstart[node + 1];
    for (int p = rs; p < re; p++) {
        int s = g_perm_src[p];
        const float* st = g_nodeT + s * 256;
        float bh0 = st[64 + lane],  bh1 = st[96 + lane];   // Bh[src]
        float eh0 = st[192 + lane], eh1 = st[224 + lane];  // Eh[src]
        float c0 = g_Ce[p * 64 + lane], c1 = g_Ce[p * 64 + 32 + lane];
        float e0 = g_e[p * 64 + lane],  e1 = g_e[p * 64 + 32 + lane];
        float t0 = c0 + d0 + eh0;
        float t1 = c1 + d1 + eh1;
        float s0 = __fdividef(1.f, 1.f + __expf(-t0));
        float s1 = __fdividef(1.f, 1.f + __expf(-t1));
        g_e[p * 64 + lane]      = e0 + fmaxf(t0, 0.f);
        g_e[p * 64 + 32 + lane] = e1 + fmaxf(t1, 0.f);
        num0 = fmaf(s0, bh0, num0);
        num1 = fmaf(s1, bh1, num1);
        den0 += s0;
        den1 += s1;
    }

    int hi = node * 64 + lane;
    float r0 = a0 + num0 * __fdividef(1.f, den0 + 1e-6f);
    float r1 = a1 + num1 * __fdividef(1.f, den1 + 1e-6f);
    g_h[hi]      += fmaxf(r0, 0.f);
    g_h[hi + 32] += fmaxf(r1, 0.f);
}

// ---------------- MLP head tail: [N,128] @ [128,2], tanh scale ----------------
__global__ void k_head(const float* __restrict__ W2, const float* __restrict__ b2,
                       float* __restrict__ out) {
    int gtid = blockIdx.x * blockDim.x + threadIdx.x;
    int n = gtid >> 5;
    if (n >= NN) return;
    int lane = gtid & 31;
    float s0 = 0.f, s1 = 0.f;
#pragma unroll
    for (int t = 0; t < 4; t++) {
        int k = lane + t * 32;
        float v = g_mlp[n * 128 + k];
        s0 = fmaf(v, W2[k * 2 + 0], s0);
        s1 = fmaf(v, W2[k * 2 + 1], s1);
    }
#pragma unroll
    for (int off = 16; off; off >>= 1) {
        s0 += __shfl_xor_sync(0xffffffffu, s0, off);
        s1 += __shfl_xor_sync(0xffffffffu, s1, off);
    }
    if (lane == 0) {
        out[n * 2 + 0] = -1.2f * tanhf(s0 + b2[0]);
        out[n * 2 + 1] = -1.2f * tanhf(s1 + b2[1]);
    }
}

// ---------------- launch ----------------
extern "C" void kernel_launch(void* const* d_in, const int* in_sizes, int n_in,
                              void* d_out, int out_size) {
    const float* h_feat  = (const float*)d_in[0];
    const float* e_feat  = (const float*)d_in[1];
    const int*   src     = (const int*)d_in[2];
    const int*   dst     = (const int*)d_in[3];
    const float* W_emb_h = (const float*)d_in[4];
    const float* b_emb_h = (const float*)d_in[5];
    const float* W_emb_e = (const float*)d_in[6];
    const float* b_emb_e = (const float*)d_in[7];
    const float* WL      = (const float*)d_in[8];
    const float* bL      = (const float*)d_in[9];
    const float* W1      = (const float*)d_in[10];
    const float* b1      = (const float*)d_in[11];
    const float* W2      = (const float*)d_in[12];
    const float* b2      = (const float*)d_in[13];
    float* out = (float*)d_out;

    void *p_h, *p_e, *p_Ce, *p_nodeT, *p_mlp;
    cudaGetSymbolAddress(&p_h, g_h);
    cudaGetSymbolAddress(&p_e, g_e);
    cudaGetSymbolAddress(&p_Ce, g_Ce);
    cudaGetSymbolAddress(&p_nodeT, g_nodeT);
    cudaGetSymbolAddress(&p_mlp, g_mlp);

    // CSR build (deterministic up to float summation order)
    k_zero<<<(NN + 255) / 256, 256>>>();
    k_hist<<<(NE + 255) / 256, 256>>>(dst);
    k_scan<<<1, 1024>>>();
    k_scatter<<<(NE + 255) / 256, 256>>>(src, dst);

    // input embeddings (e in CSR order)
    k_embed_h<<<(NN * HID + 255) / 256, 256>>>(h_feat, W_emb_h, b_emb_h);
    k_embed_e<<<(NE * HID + 255) / 256, 256>>>(e_feat, W_emb_e, b_emb_e);

    for (int l = 0; l < LAYERS; l++) {
        const float* Wl = WL + (size_t)l * 5 * HID * HID;
        const float* bl = bL + (size_t)l * 5 * HID;
        // node transforms A,B,D,E -> g_nodeT [node][4][64]
        k_gemm64<<<dim3((NN + 63) / 64, 4), 256>>>(
            (const float*)p_h, Wl, bl, (float*)p_nodeT, NN, 64, 4096, 256, 0);
        // edge transform Ce = e @ Wl[4] + bl[4]
        k_gemm64<<<dim3(NE / 64, 1), 256>>>(
            (const float*)p_e, Wl + 4 * 4096, bl + 4 * 64, (float*)p_Ce, NE, 64, 0, 64, 0);
        // fused gate + segment-sum + residual updates for e and h
        k_edge<<<(NN * 32 + 255) / 256, 256>>>();
    }

    // MLP head
    k_gemm64<<<dim3((NN + 63) / 64, 2), 256>>>(
        (const float*)p_h, W1, b1, (float*)p_mlp, NN, 128, 64, 128, 1);
    k_head<<<(NN * 32 + 255) / 256, 256>>>(W2, b2, out);
}

// round 2
// speedup vs baseline: 1.1468x; 1.1468x over previous
#include <cuda_runtime.h>
#include <math.h>

#define NN 50000
#define NE 800000
#define HID 64
#define LAYERS 4
#define MLPH 128

typedef unsigned long long ull;

// ---------------- device state ----------------
__device__ float g_h[NN * HID];
__device__ float g_e[NE * HID];            // edge state, CSR-permuted order
__device__ float g_sig[NE * HID];          // sigma per edge (CSR order)
__device__ float g_nodeT[NN * 4 * HID];    // per node: [A|B|D|E]
__device__ float g_mlp[NN * MLPH];
__device__ int   g_count[NN];
__device__ int   g_rowstart[NN + 1];
__device__ int   g_cursor[NN];
__device__ int   g_perm_src[NE];
__device__ int   g_perm_dst[NE];
__device__ int   g_perm_eid[NE];

// ---------------- f32x2 packed helpers ----------------
__device__ __forceinline__ ull pack2(float x, float y) {
    ull r; asm("mov.b64 %0, {%1, %2};" : "=l"(r) : "f"(x), "f"(y)); return r;
}
__device__ __forceinline__ void ffma2(ull& acc, ull a, ull b) {
    asm("fma.rn.f32x2 %0, %1, %2, %0;" : "+l"(acc) : "l"(a), "l"(b));
}
__device__ __forceinline__ float2 unpack2(ull v) {
    float x, y; asm("mov.b64 {%0, %1}, %2;" : "=f"(x), "=f"(y) : "l"(v));
    return make_float2(x, y);
}
__device__ __forceinline__ float fsig(float t) {
    return __fdividef(1.f, 1.f + __expf(-t));
}

// ---------------- CSR build ----------------
__global__ void k_zero() {
    int i = blockIdx.x * blockDim.x + threadIdx.x;
    if (i < NN) g_count[i] = 0;
}
__global__ void k_hist(const int* __restrict__ dst) {
    int e = blockIdx.x * blockDim.x + threadIdx.x;
    if (e < NE) atomicAdd(&g_count[dst[e]], 1);
}
__global__ void k_scan() {
    __shared__ int part[1024];
    int tid = threadIdx.x;
    const int CH = (NN + 1023) / 1024;
    int base = tid * CH;
    int s = 0;
    for (int i = 0; i < CH; i++) { int idx = base + i; if (idx < NN) s += g_count[idx]; }
    part[tid] = s;
    __syncthreads();
    for (int off = 1; off < 1024; off <<= 1) {
        int v = (tid >= off) ? part[tid - off] : 0;
        __syncthreads();
        part[tid] += v;
        __syncthreads();
    }
    int excl = part[tid] - s;
    for (int i = 0; i < CH; i++) {
        int idx = base + i;
        if (idx < NN) { g_rowstart[idx] = excl; g_cursor[idx] = excl; excl += g_count[idx]; }
    }
    if (tid == 1023) g_rowstart[NN] = part[1023];
}
__global__ void k_scatter(const int* __restrict__ src, const int* __restrict__ dst) {
    int e = blockIdx.x * blockDim.x + threadIdx.x;
    if (e < NE) {
        int d = dst[e];
        int pos = atomicAdd(&g_cursor[d], 1);
        g_perm_src[pos] = src[e];
        g_perm_dst[pos] = d;
        g_perm_eid[pos] = e;
    }
}

// ---------------- input embeddings ----------------
__global__ void k_embed_h(const float* __restrict__ hf, const float* __restrict__ W,
                          const float* __restrict__ b) {
    int idx = blockIdx.x * blockDim.x + threadIdx.x;
    if (idx >= NN * HID) return;
    int n = idx >> 6, c = idx & 63;
    float s = b[c];
#pragma unroll
    for (int j = 0; j < 6; j++) s = fmaf(hf[n * 6 + j], W[j * HID + c], s);
    g_h[idx] = s;
}
__global__ void k_embed_e(const float* __restrict__ ef, const float* __restrict__ W,
                          const float* __restrict__ b) {
    int idx = blockIdx.x * blockDim.x + threadIdx.x;
    if (idx >= NE * HID) return;
    int p = idx >> 6, c = idx & 63;
    int eid = g_perm_eid[p];
    float s = b[c];
    s = fmaf(ef[eid * 2 + 0], W[c], s);
    s = fmaf(ef[eid * 2 + 1], W[HID + c], s);
    g_e[idx] = s;
}

// ---------------- GEMM core macro: 4k-unrolled, fma-bound ----------------
// Requires: __shared__ float As[64][68], Ws[64][68]; int tx, ty; ull acc[4][2].
#define GEMM_CORE() do {                                                     \
    _Pragma("unroll")                                                        \
    for (int k4 = 0; k4 < 64; k4 += 4) {                                     \
        ull bp[4][2];                                                        \
        _Pragma("unroll")                                                    \
        for (int j = 0; j < 4; j++) {                                        \
            float4 b4 = *(const float4*)&Ws[k4 + j][tx * 4];                 \
            bp[j][0] = pack2(b4.x, b4.y);                                    \
            bp[j][1] = pack2(b4.z, b4.w);                                    \
        }                                                                    \
        _Pragma("unroll")                                                    \
        for (int r = 0; r < 4; r++) {                                        \
            float4 a4 = *(const float4*)&As[ty * 4 + r][k4];                 \
            ull ap0 = pack2(a4.x, a4.x), ap1 = pack2(a4.y, a4.y);            \
            ull ap2 = pack2(a4.z, a4.z), ap3 = pack2(a4.w, a4.w);            \
            ffma2(acc[r][0], ap0, bp[0][0]); ffma2(acc[r][1], ap0, bp[0][1]);\
            ffma2(acc[r][0], ap1, bp[1][0]); ffma2(acc[r][1], ap1, bp[1][1]);\
            ffma2(acc[r][0], ap2, bp[2][0]); ffma2(acc[r][1], ap2, bp[2][1]);\
            ffma2(acc[r][0], ap3, bp[3][0]); ffma2(acc[r][1], ap3, bp[3][1]);\
        }                                                                    \
    }                                                                        \
} while (0)

// ---------------- generic GEMM: C[M,*] = A[M,64] @ W[64,64-tile] + bias ----------------
__global__ void __launch_bounds__(256) k_gemm64(
    const float* __restrict__ A, const float* __restrict__ W,
    const float* __restrict__ bias, float* __restrict__ C,
    int M, int ldw, int wtStride, int ldc, int relu)
{
    __shared__ float As[64][68];
    __shared__ float Ws[64][68];
    int by = blockIdx.y;
    const float* Wt = W + (size_t)by * wtStride;
    int n0 = blockIdx.x * 64;
    int t = threadIdx.x;
    int tx = t & 15, ty = t >> 4;

#pragma unroll
    for (int i = 0; i < 4; i++) {
        int q = i * 256 + t;
        int row = q >> 4, kq = q & 15;
        int m = n0 + row;
        float4 v = make_float4(0.f, 0.f, 0.f, 0.f);
        if (m < M) v = *(const float4*)(A + (size_t)m * 64 + kq * 4);
        *(float4*)&As[row][kq * 4] = v;
    }
#pragma unroll
    for (int i = 0; i < 4; i++) {
        int q = i * 256 + t;
        int k = q >> 4, cq = q & 15;
        float4 v = *(const float4*)(Wt + (size_t)k * ldw + cq * 4);
        *(float4*)&Ws[k][cq * 4] = v;
    }
    __syncthreads();

    ull acc[4][2];
#pragma unroll
    for (int r = 0; r < 4; r++) { acc[r][0] = 0ull; acc[r][1] = 0ull; }

    GEMM_CORE();

    float bb0 = bias[by * 64 + tx * 4 + 0];
    float bb1 = bias[by * 64 + tx * 4 + 1];
    float bb2 = bias[by * 64 + tx * 4 + 2];
    float bb3 = bias[by * 64 + tx * 4 + 3];
#pragma unroll
    for (int r = 0; r < 4; r++) {
        int m = n0 + ty * 4 + r;
        if (m < M) {
            float2 v0 = unpack2(acc[r][0]);
            float2 v1 = unpack2(acc[r][1]);
            float4 o;
            o.x = v0.x + bb0; o.y = v0.y + bb1;
            o.z = v1.x + bb2; o.w = v1.y + bb3;
            if (relu) {
                o.x = fmaxf(o.x, 0.f); o.y = fmaxf(o.y, 0.f);
                o.z = fmaxf(o.z, 0.f); o.w = fmaxf(o.w, 0.f);
            }
            *(float4*)(C + (size_t)m * ldc + by * 64 + tx * 4) = o;
        }
    }
}

// ---------------- fused edge GEMM: Ce = e @ Wc, then gate + e-residual ----------------
// One block = 64 consecutive CSR positions. Epilogue gathers Dh[dst], Eh[src],
// computes e_hat, writes sigma; updates e in place (skipped on last layer).
__global__ void __launch_bounds__(256) k_edge_gemm(
    const float* __restrict__ Wc, const float* __restrict__ bc, int last)
{
    __shared__ float As[64][68];
    __shared__ float Ws[64][68];
    __shared__ int sSrc[64], sDst[64];
    int p0 = blockIdx.x * 64;
    int t = threadIdx.x;
    int tx = t & 15, ty = t >> 4;

    if (t < 64) {
        sSrc[t] = g_perm_src[p0 + t];
        sDst[t] = g_perm_dst[p0 + t];
    }
#pragma unroll
    for (int i = 0; i < 4; i++) {
        int q = i * 256 + t;
        int row = q >> 4, kq = q & 15;
        *(float4*)&As[row][kq * 4] = *(const float4*)(g_e + (size_t)(p0 + row) * 64 + kq * 4);
    }
#pragma unroll
    for (int i = 0; i < 4; i++) {
        int q = i * 256 + t;
        int k = q >> 4, cq = q & 15;
        *(float4*)&Ws[k][cq * 4] = *(const float4*)(Wc + (size_t)k * 64 + cq * 4);
    }
    __syncthreads();

    ull acc[4][2];
#pragma unroll
    for (int r = 0; r < 4; r++) { acc[r][0] = 0ull; acc[r][1] = 0ull; }

    GEMM_CORE();

    float bb0 = bc[tx * 4 + 0], bb1 = bc[tx * 4 + 1];
    float bb2 = bc[tx * 4 + 2], bb3 = bc[tx * 4 + 3];

#pragma unroll
    for (int r = 0; r < 4; r++) {
        int row = ty * 4 + r;
        int p = p0 + row;
        int dn = sDst[row], sn = sSrc[row];
        float4 dh = *(const float4*)(g_nodeT + (size_t)dn * 256 + 128 + tx * 4);
        float4 eh = *(const float4*)(g_nodeT + (size_t)sn * 256 + 192 + tx * 4);
        float2 v0 = unpack2(acc[r][0]);
        float2 v1 = unpack2(acc[r][1]);
        float t0 = v0.x + bb0 + dh.x + eh.x;
        float t1 = v0.y + bb1 + dh.y + eh.y;
        float t2 = v1.x + bb2 + dh.z + eh.z;
        float t3 = v1.y + bb3 + dh.w + eh.w;
        float4 sg = make_float4(fsig(t0), fsig(t1), fsig(t2), fsig(t3));
        *(float4*)(g_sig + (size_t)p * 64 + tx * 4) = sg;
        if (!last) {
            float4 eo = *(const float4*)&As[row][tx * 4];
            float4 en;
            en.x = eo.x + fmaxf(t0, 0.f);
            en.y = eo.y + fmaxf(t1, 0.f);
            en.z = eo.z + fmaxf(t2, 0.f);
            en.w = eo.w + fmaxf(t3, 0.f);
            *(float4*)(g_e + (size_t)p * 64 + tx * 4) = en;
        }
    }
}

// ---------------- reduction: num/den segment-sum + node residual update ----------------
__global__ void k_reduce() {
    int gtid = blockIdx.x * blockDim.x + threadIdx.x;
    int node = gtid >> 5;
    if (node >= NN) return;
    int lane = gtid & 31;

    const float* nt = g_nodeT + (size_t)node * 256;
    float a0 = nt[lane], a1 = nt[32 + lane];          // Ah
    float num0 = 0.f, num1 = 0.f, den0 = 0.f, den1 = 0.f;

    int rs = g_rowstart[node], re = g_rowstart[node + 1];
    for (int p = rs; p < re; p++) {
        int s = g_perm_src[p];
        const float* st = g_nodeT + (size_t)s * 256;
        float bh0 = st[64 + lane], bh1 = st[96 + lane];
        float s0 = g_sig[(size_t)p * 64 + lane];
        float s1 = g_sig[(size_t)p * 64 + 32 + lane];
        num0 = fmaf(s0, bh0, num0);
        num1 = fmaf(s1, bh1, num1);
        den0 += s0;
        den1 += s1;
    }

    int hi = node * 64 + lane;
    float r0 = a0 + num0 * __fdividef(1.f, den0 + 1e-6f);
    float r1 = a1 + num1 * __fdividef(1.f, den1 + 1e-6f);
    g_h[hi]      += fmaxf(r0, 0.f);
    g_h[hi + 32] += fmaxf(r1, 0.f);
}

// ---------------- MLP head tail ----------------
__global__ void k_head(const float* __restrict__ W2, const float* __restrict__ b2,
                       float* __restrict__ out) {
    int gtid = blockIdx.x * blockDim.x + threadIdx.x;
    int n = gtid >> 5;
    if (n >= NN) return;
    int lane = gtid & 31;
    float s0 = 0.f, s1 = 0.f;
#pragma unroll
    for (int t = 0; t < 4; t++) {
        int k = lane + t * 32;
        float v = g_mlp[n * 128 + k];
        s0 = fmaf(v, W2[k * 2 + 0], s0);
        s1 = fmaf(v, W2[k * 2 + 1], s1);
    }
#pragma unroll
    for (int off = 16; off; off >>= 1) {
        s0 += __shfl_xor_sync(0xffffffffu, s0, off);
        s1 += __shfl_xor_sync(0xffffffffu, s1, off);
    }
    if (lane == 0) {
        out[n * 2 + 0] = -1.2f * tanhf(s0 + b2[0]);
        out[n * 2 + 1] = -1.2f * tanhf(s1 + b2[1]);
    }
}

// ---------------- launch ----------------
extern "C" void kernel_launch(void* const* d_in, const int* in_sizes, int n_in,
                              void* d_out, int out_size) {
    const float* h_feat  = (const float*)d_in[0];
    const float* e_feat  = (const float*)d_in[1];
    const int*   src     = (const int*)d_in[2];
    const int*   dst     = (const int*)d_in[3];
    const float* W_emb_h = (const float*)d_in[4];
    const float* b_emb_h = (const float*)d_in[5];
    const float* W_emb_e = (const float*)d_in[6];
    const float* b_emb_e = (const float*)d_in[7];
    const float* WL      = (const float*)d_in[8];
    const float* bL      = (const float*)d_in[9];
    const float* W1      = (const float*)d_in[10];
    const float* b1      = (const float*)d_in[11];
    const float* W2      = (const float*)d_in[12];
    const float* b2      = (const float*)d_in[13];
    float* out = (float*)d_out;

    void *p_h, *p_nodeT, *p_mlp;
    cudaGetSymbolAddress(&p_h, g_h);
    cudaGetSymbolAddress(&p_nodeT, g_nodeT);
    cudaGetSymbolAddress(&p_mlp, g_mlp);

    // CSR build
    k_zero<<<(NN + 255) / 256, 256>>>();
    k_hist<<<(NE + 255) / 256, 256>>>(dst);
    k_scan<<<1, 1024>>>();
    k_scatter<<<(NE + 255) / 256, 256>>>(src, dst);

    // input embeddings (e in CSR order)
    k_embed_h<<<(NN * HID + 255) / 256, 256>>>(h_feat, W_emb_h, b_emb_h);
    k_embed_e<<<(NE * HID + 255) / 256, 256>>>(e_feat, W_emb_e, b_emb_e);

    for (int l = 0; l < LAYERS; l++) {
        const float* Wl = WL + (size_t)l * 5 * HID * HID;
        const float* bl = bL + (size_t)l * 5 * HID;
        // node transforms A,B,D,E -> g_nodeT
        k_gemm64<<<dim3((NN + 63) / 64, 4), 256>>>(
            (const float*)p_h, Wl, bl, (float*)p_nodeT, NN, 64, 4096, 256, 0);
        // fused edge transform + gate + e-residual (+ sigma for reduction)
        k_edge_gemm<<<NE / 64, 256>>>(Wl + 4 * 4096, bl + 4 * 64, l == LAYERS - 1);
        // segment reduction + h residual
        k_reduce<<<(NN * 32 + 255) / 256, 256>>>();
    }

    // MLP head
    k_gemm64<<<dim3((NN + 63) / 64, 2), 256>>>(
        (const float*)p_h, W1, b1, (float*)p_mlp, NN, 128, 64, 128, 1);
    k_head<<<(NN * 32 + 255) / 256, 256>>>(W2, b2, out);
}